// round 17
// baseline (speedup 1.0000x reference)
#include <cuda_runtime.h>

// Aggre_81226421502275: y[n] = mean_k( relu(mailbox[n,k,:]@W1 + b1) @ W2 + b2 )
// N=500000, K=16, F_IN=7, F_HID=40, F_OUT=3. fp32.
//
// R14: scalar-fp32 floor is ~69us of FFMA2 (measured invariant across R12/R13).
// Drive fma utilization up: low-register kernel (weights streamed from shared as
// LDS.128 quads) + R12 staging + duplicated packing -> ~5 CTAs/SM.
//  - 2 threads/node, each owns 20 hidden units (10 packed pairs)
//  - mailbox staged duplicated ({x,x},{y,y},...), row stride 226 floats:
//    conflict-free broadcast LDS.64, no bcast MOVs
//  - W1 pairs contiguous -> LDS.128 gives 2 hidden pairs per load; the two jh
//    groups hit disjoint banks (offset 80B) -> 1 wavefront
//  - bias pairs hoisted to registers; packed relu (alu pipe) + add2 accumulate

#define KK    16
#define FIN   7
#define FHID  40
#define FOUT  3
#define NPB   48            // nodes per block
#define TPB   96            // 2 threads per node
#define ROWSD 226           // duplicated row stride in floats (224 used + 2 pad)
#define JPT   10            // hidden pairs per thread

typedef unsigned long long u64;
typedef unsigned int       u32;

__device__ __forceinline__ u64 pack2(float x, float y) {
    u64 r; asm("mov.b64 %0, {%1, %2};" : "=l"(r) : "f"(x), "f"(y)); return r;
}
__device__ __forceinline__ void unpack2(u64 v, float &x, float &y) {
    asm("mov.b64 {%0, %1}, %2;" : "=f"(x), "=f"(y) : "l"(v));
}
__device__ __forceinline__ u64 fma2(u64 a, u64 b, u64 c) {
    u64 d; asm("fma.rn.f32x2 %0, %1, %2, %3;" : "=l"(d) : "l"(a), "l"(b), "l"(c)); return d;
}
__device__ __forceinline__ u64 add2(u64 a, u64 b) {
    u64 d; asm("add.rn.f32x2 %0, %1, %2;" : "=l"(d) : "l"(a), "l"(b)); return d;
}
// packed relu: zero each fp32 half whose sign bit is set (alu pipe: SHF+LOP3 x2)
__device__ __forceinline__ u64 relu2(u64 v) {
    u32 lo, hi;
    asm("mov.b64 {%0, %1}, %2;" : "=r"(lo), "=r"(hi) : "l"(v));
    lo &= ~(u32)((int)lo >> 31);
    hi &= ~(u32)((int)hi >> 31);
    u64 r; asm("mov.b64 %0, {%1, %2};" : "=l"(r) : "r"(lo), "r"(hi));
    return r;
}

__global__ __launch_bounds__(TPB)
void aggre_mlp_kernel(const float* __restrict__ mailbox,
                      const float* __restrict__ W1,
                      const float* __restrict__ b1,
                      const float* __restrict__ W2,
                      const float* __restrict__ b2,
                      float* __restrict__ out,
                      int N)
{
    __shared__ float smb[NPB * ROWSD];        // duplicated mailbox rows (43.4 KB)
    __shared__ u64   sW1p[FIN * (FHID / 2)];  // [f][jp] = (W1[f][2jp], W1[f][2jp+1]), 16B-groupable
    __shared__ u64   sb1p[FHID / 2];
    __shared__ float sW2[FHID * FOUT];        // row-major [j][o]
    __shared__ float sb2[FOUT];

    const int tid = threadIdx.x;

    // ---- weight prep ----
    for (int i = tid; i < FIN * (FHID / 2); i += TPB)
        sW1p[i] = pack2(W1[2 * i], W1[2 * i + 1]);
    if (tid < FHID / 2) sb1p[tid] = pack2(b1[2 * tid], b1[2 * tid + 1]);
    for (int i = tid; i < FHID * FOUT; i += TPB) sW2[i] = W2[i];
    if (tid < FOUT) sb2[tid] = b2[tid];

    // ---- stage mailbox duplicated: 48 nodes x 112 floats -> {x,x},{y,y},... ----
    const int node0 = blockIdx.x * NPB;
    const int valid = min(NPB, N - node0);
    const int vq    = valid * (KK * FIN / 4);               // valid float4 count
    const float4* gsrc = reinterpret_cast<const float4*>(mailbox + (long long)node0 * (KK * FIN));
#pragma unroll
    for (int i = 0; i < (NPB * KK * FIN / 4) / TPB; i++) { // 14 iterations
        int idx = i * TPB + tid;
        if (idx >= vq) idx = vq - 1;                        // clamp (benign dup stores)
        const float4 v = gsrc[idx];
        const int fidx = idx * 4;
        const int node = fidx / (KK * FIN);
        const int off  = fidx - node * (KK * FIN);
        float2* d = reinterpret_cast<float2*>(&smb[node * ROWSD + 2 * off]); // 8B-aligned
        d[0] = make_float2(v.x, v.x);
        d[1] = make_float2(v.y, v.y);
        d[2] = make_float2(v.z, v.z);
        d[3] = make_float2(v.w, v.w);
    }
    __syncthreads();

    // ---- compute: 2 threads/node, each 10 hidden pairs ----
    const int nl    = tid >> 1;                // local node 0..47
    const int jh    = tid & 1;                 // hidden half
    const int n     = node0 + nl;
    const bool live = (n < N);
    const int nlc   = live ? nl : 0;
    const int jpb   = jh * JPT;                // first hidden pair (0 or 10; even -> 16B aligned)

    // Bias pairs hoisted (10 u64 = 20 regs).
    u64 bb[JPT];
#pragma unroll
    for (int q = 0; q < JPT; q++) bb[q] = sb1p[jpb + q];

    u64 hs[JPT];
#pragma unroll
    for (int q = 0; q < JPT; q++) hs[q] = 0ull;

    const u64* mrow = reinterpret_cast<const u64*>(&smb[nlc * ROWSD]);

#pragma unroll 1
    for (int t = 0; t < KK / 2; t++) {
        // two messages, features pre-broadcast-packed in shared
        u64 m0[FIN], m1[FIN];
#pragma unroll
        for (int f = 0; f < FIN; f++) {
            m0[f] = mrow[t * (2 * FIN) + f];
            m1[f] = mrow[t * (2 * FIN) + FIN + f];
        }

        // hidden pairs two-at-a-time: LDS.128 -> (pair p0, pair p0+1) for one f
#pragma unroll
        for (int qq = 0; qq < JPT / 2; qq++) {
            const int p0 = jpb + 2 * qq;
            u64 a0x = bb[2 * qq],     a1x = bb[2 * qq];
            u64 a0y = bb[2 * qq + 1], a1y = bb[2 * qq + 1];
#pragma unroll
            for (int f = 0; f < FIN; f++) {
                const ulonglong2 wq =
                    *reinterpret_cast<const ulonglong2*>(&sW1p[f * (FHID / 2) + p0]);
                a0x = fma2(m0[f], wq.x, a0x);
                a0y = fma2(m0[f], wq.y, a0y);
                a1x = fma2(m1[f], wq.x, a1x);
                a1y = fma2(m1[f], wq.y, a1y);
            }
            hs[2 * qq]     = add2(hs[2 * qq],     add2(relu2(a0x), relu2(a1x)));
            hs[2 * qq + 1] = add2(hs[2 * qq + 1], add2(relu2(a0y), relu2(a1y)));
        }
    }

    // ---- layer 2 on this thread's 20 hidden units, combine across the pair ----
    float y0 = 0.0f, y1 = 0.0f, y2 = 0.0f;
#pragma unroll
    for (int q = 0; q < JPT; q++) {
        const int j = 2 * (jpb + q);
        float h0, h1;
        unpack2(hs[q], h0, h1);
        y0 = fmaf(h0, sW2[j * FOUT + 0], y0);
        y1 = fmaf(h0, sW2[j * FOUT + 1], y1);
        y2 = fmaf(h0, sW2[j * FOUT + 2], y2);
        y0 = fmaf(h1, sW2[(j + 1) * FOUT + 0], y0);
        y1 = fmaf(h1, sW2[(j + 1) * FOUT + 1], y1);
        y2 = fmaf(h1, sW2[(j + 1) * FOUT + 2], y2);
    }

    y0 += __shfl_xor_sync(0xffffffffu, y0, 1);
    y1 += __shfl_xor_sync(0xffffffffu, y1, 1);
    y2 += __shfl_xor_sync(0xffffffffu, y2, 1);

    if (live && jh == 0) {
        const float inv = 1.0f / (float)KK;
        out[n * FOUT + 0] = fmaf(y0, inv, sb2[0]);
        out[n * FOUT + 1] = fmaf(y1, inv, sb2[1]);
        out[n * FOUT + 2] = fmaf(y2, inv, sb2[2]);
    }
}

extern "C" void kernel_launch(void* const* d_in, const int* in_sizes, int n_in,
                              void* d_out, int out_size)
{
    const float* mailbox = (const float*)d_in[0];
    const float* W1      = (const float*)d_in[1];
    const float* b1      = (const float*)d_in[2];
    const float* W2      = (const float*)d_in[3];
    const float* b2      = (const float*)d_in[4];
    float*       out     = (float*)d_out;

    const int N = in_sizes[0] / (KK * FIN);
    const int blocks = (N + NPB - 1) / NPB;
    aggre_mlp_kernel<<<blocks, TPB>>>(mailbox, W1, b1, W2, b2, out, N);
}